// round 13
// baseline (speedup 1.0000x reference)
#include <cuda_runtime.h>
#include <cuda_bf16.h>
#include <cstdint>

#define NN   50000
#define NPAD 50048
#define EE   800000
#define HC   128
#define CCH  64
#define ED   32

// ---- scratch (static __device__ arrays; no allocations allowed) ----
__device__ __align__(256) __nv_bfloat16 g_xh[NPAD * 128];
__device__ __align__(256) __nv_bfloat16 g_xl[NPAD * 128];
__device__ __align__(256) __nv_bfloat16 g_Bh[640 * 128];   // [out_col][k]; rows 512-575 = Wqe, 576-639 = 0
__device__ __align__(256) __nv_bfloat16 g_Bl[640 * 128];
__device__ float g_bqe[64];
__device__ float g_q[NN * HC];
__device__ float g_k[NN * HC];
__device__ float g_v[NN * HC];
__device__ float g_qwe[NN * 64];      // [n][h*32+d]
__device__ int   g_deg[NN];
__device__ int   g_off[NN + 1];
__device__ int   g_cur[NN];
__device__ int2  g_se[EE];            // (src, eid) CSR-sorted by dst

// ================= prep: split-bf16 conversion =================
__global__ void prep_x_kernel(const float* __restrict__ x)
{
    int idx = blockIdx.x * blockDim.x + threadIdx.x;
    if (idx >= NPAD * 128) return;
    float v = (idx < NN * 128) ? x[idx] : 0.f;
    __nv_bfloat16 hi = __float2bfloat16(v);
    g_xh[idx] = hi;
    g_xl[idx] = __float2bfloat16(v - __bfloat162float(hi));
}

// rows 0-511: split transposed {Wq,Wk,Wv,Wskip}; rows 576-639: zero.
__global__ void prep_w_kernel(const float* __restrict__ Wq, const float* __restrict__ Wk,
                              const float* __restrict__ Wv, const float* __restrict__ Wskip)
{
    int idx = blockIdx.x * blockDim.x + threadIdx.x;
    if (idx >= 640 * 128) return;
    int n = idx >> 7, k = idx & 127;
    if (n >= 576) { g_Bh[idx] = __float2bfloat16(0.f); g_Bl[idx] = __float2bfloat16(0.f); return; }
    if (n >= 512) return;   // filled by prep_qe
    int m = n >> 7, col = n & 127;
    const float* W = (m == 0) ? Wq : (m == 1) ? Wk : (m == 2) ? Wv : Wskip;
    float v = W[k * 128 + col];
    __nv_bfloat16 hi = __float2bfloat16(v);
    g_Bh[idx] = hi;
    g_Bl[idx] = __float2bfloat16(v - __bfloat162float(hi));
}

// Wqe[k, h*32+d] = sum_c Wq[k, h*64+c] * We[d, h*64+c];  bqe[h*32+d] = sum_c bq[h*64+c]*We[d,h*64+c]
__global__ void prep_qe_kernel(const float* __restrict__ Wq, const float* __restrict__ bq,
                               const float* __restrict__ We)
{
    int idx = blockIdx.x * blockDim.x + threadIdx.x;
    if (idx >= 64 * 128) return;
    int j = idx >> 7, kk = idx & 127;     // j = h*32+d
    int h = j >> 5, d = j & 31;
    const float* wq = &Wq[kk * 128 + h * 64];
    const float* we = &We[d * 128 + h * 64];
    float s = 0.f;
    #pragma unroll
    for (int c = 0; c < 64; c++) s += wq[c] * we[c];
    __nv_bfloat16 hi = __float2bfloat16(s);
    g_Bh[(512 + j) * 128 + kk] = hi;
    g_Bl[(512 + j) * 128 + kk] = __float2bfloat16(s - __bfloat162float(hi));
    if (idx < 64) {
        int hh = idx >> 5, dd = idx & 31;
        float b = 0.f;
        #pragma unroll
        for (int c = 0; c < 64; c++) b += bq[hh * 64 + c] * We[dd * 128 + hh * 64 + c];
        g_bqe[idx] = b;
    }
}

// ================= fused projection GEMM via mma.sync (HMMA bf16) =================
// grid = (NPAD/128, 5); y: 0=q 1=k 2=v 3=skip 4=qwe(N=64). Split-bf16 fp32-acc.
#define PA 136
#define A_TILE_B  (128 * PA * 2)
#define OFF_XH    0
#define OFF_XL    (A_TILE_B)
#define OFF_BHH   (2 * A_TILE_B)
#define OFF_BLL   (3 * A_TILE_B)
#define OFF_BIAS  (4 * A_TILE_B)
#define GEMM_SMEM (OFF_BIAS + 512)

__device__ __forceinline__ void mma16816(float* d, const uint32_t* a, const uint32_t* b)
{
    asm volatile(
        "mma.sync.aligned.m16n8k16.row.col.f32.bf16.bf16.f32 "
        "{%0,%1,%2,%3}, {%4,%5,%6,%7}, {%8,%9}, {%0,%1,%2,%3};"
        : "+f"(d[0]), "+f"(d[1]), "+f"(d[2]), "+f"(d[3])
        : "r"(a[0]), "r"(a[1]), "r"(a[2]), "r"(a[3]), "r"(b[0]), "r"(b[1]));
}

__global__ void __launch_bounds__(256, 1)
gemm_kernel(const float* __restrict__ bq, const float* __restrict__ bk,
            const float* __restrict__ bv, const float* __restrict__ bskip,
            float* __restrict__ out)
{
    extern __shared__ char sm[];
    __nv_bfloat16* Axh = (__nv_bfloat16*)(sm + OFF_XH);
    __nv_bfloat16* Axl = (__nv_bfloat16*)(sm + OFF_XL);
    __nv_bfloat16* Bsh = (__nv_bfloat16*)(sm + OFF_BHH);
    __nv_bfloat16* Bsl = (__nv_bfloat16*)(sm + OFF_BLL);
    float* biasS = (float*)(sm + OFF_BIAS);

    const int tid  = threadIdx.x;
    const int wid  = tid >> 5;
    const int lane = tid & 31;
    const int m0   = blockIdx.x * 128;
    const int y    = blockIdx.y;
    const int n0   = y * 128;

    for (int u = tid; u < 2048; u += 256) {
        int r = u >> 4, c = (u & 15) * 8;
        size_t go = (size_t)(m0 + r) * 128 + c;
        *(uint4*)&Axh[r * PA + c] = *(const uint4*)&g_xh[go];
        *(uint4*)&Axl[r * PA + c] = *(const uint4*)&g_xl[go];
    }
    for (int u = tid; u < 2048; u += 256) {
        int r = u >> 4, c = (u & 15) * 8;
        size_t go = (size_t)(n0 + r) * 128 + c;
        *(uint4*)&Bsh[r * PA + c] = *(const uint4*)&g_Bh[go];
        *(uint4*)&Bsl[r * PA + c] = *(const uint4*)&g_Bl[go];
    }
    if (tid < 128) {
        float b;
        if      (y == 0) b = bq[tid];
        else if (y == 1) b = bk[tid];
        else if (y == 2) b = bv[tid];
        else if (y == 3) b = bskip[tid];
        else             b = (tid < 64) ? g_bqe[tid] : 0.f;
        biasS[tid] = b;
    }
    __syncthreads();

    const int wm = wid & 3;
    const int wn = wid >> 2;
    const int g  = lane >> 2;
    const int t  = lane & 3;

    float acc[2][8][4];
    #pragma unroll
    for (int i = 0; i < 2; i++)
        #pragma unroll
        for (int j = 0; j < 8; j++)
            #pragma unroll
            for (int l = 0; l < 4; l++) acc[i][j][l] = 0.f;

    const __nv_bfloat16* Ap[3] = { Axh, Axl, Axh };
    const __nv_bfloat16* Bp[3] = { Bsh, Bsh, Bsl };

    #pragma unroll
    for (int p = 0; p < 3; p++) {
        const __nv_bfloat16* As = Ap[p];
        const __nv_bfloat16* Bs = Bp[p];
        #pragma unroll
        for (int ks = 0; ks < 8; ks++) {
            const int k0 = ks * 16;
            uint32_t a[2][4], b[8][2];
            #pragma unroll
            for (int mt = 0; mt < 2; mt++) {
                const int rm = wm * 32 + mt * 16 + g;
                a[mt][0] = *(const uint32_t*)&As[rm * PA + k0 + t * 2];
                a[mt][1] = *(const uint32_t*)&As[(rm + 8) * PA + k0 + t * 2];
                a[mt][2] = *(const uint32_t*)&As[rm * PA + k0 + t * 2 + 8];
                a[mt][3] = *(const uint32_t*)&As[(rm + 8) * PA + k0 + t * 2 + 8];
            }
            #pragma unroll
            for (int nt = 0; nt < 8; nt++) {
                const int cn = wn * 64 + nt * 8 + g;
                b[nt][0] = *(const uint32_t*)&Bs[cn * PA + k0 + t * 2];
                b[nt][1] = *(const uint32_t*)&Bs[cn * PA + k0 + t * 2 + 8];
            }
            #pragma unroll
            for (int mt = 0; mt < 2; mt++)
                #pragma unroll
                for (int nt = 0; nt < 8; nt++)
                    mma16816(acc[mt][nt], a[mt], b[nt]);
        }
    }

    // epilogue: direct biased float2 stores
    float* dst; int stride, ncols;
    if      (y == 0) { dst = g_q;   stride = 128; ncols = 128; }
    else if (y == 1) { dst = g_k;   stride = 128; ncols = 128; }
    else if (y == 2) { dst = g_v;   stride = 128; ncols = 128; }
    else if (y == 3) { dst = out;   stride = 128; ncols = 128; }
    else             { dst = g_qwe; stride = 64;  ncols = 64;  }

    #pragma unroll
    for (int mt = 0; mt < 2; mt++) {
        const int r0 = m0 + wm * 32 + mt * 16 + g;
        #pragma unroll
        for (int nt = 0; nt < 8; nt++) {
            const int c = wn * 64 + nt * 8 + t * 2;
            if (c >= ncols) continue;
            const float b0 = biasS[c], b1 = biasS[c + 1];
            if (r0 < NN)
                *(float2*)&dst[(size_t)r0 * stride + c] =
                    make_float2(acc[mt][nt][0] + b0, acc[mt][nt][1] + b1);
            if (r0 + 8 < NN)
                *(float2*)&dst[(size_t)(r0 + 8) * stride + c] =
                    make_float2(acc[mt][nt][2] + b0, acc[mt][nt][3] + b1);
        }
    }
}

// ---------------- CSR build ----------------
__global__ void zero_deg_kernel()
{
    int i = blockIdx.x * blockDim.x + threadIdx.x;
    if (i < NN) g_deg[i] = 0;
}

__global__ void hist_kernel(const int* __restrict__ ei)
{
    int e = blockIdx.x * blockDim.x + threadIdx.x;
    if (e < EE) atomicAdd(&g_deg[ei[EE + e]], 1);
}

__global__ void scan_kernel()
{
    const int tid  = threadIdx.x;
    const int lane = tid & 31;
    const int wid  = tid >> 5;
    __shared__ int wsum[32];
    __shared__ int s_carry;
    if (tid == 0) s_carry = 0;
    __syncthreads();

    for (int base = 0; base < NN; base += 1024) {
        int i = base + tid;
        int v = (i < NN) ? g_deg[i] : 0;

        int x = v;
        #pragma unroll
        for (int o = 1; o < 32; o <<= 1) {
            int y = __shfl_up_sync(0xffffffffu, x, o);
            if (lane >= o) x += y;
        }
        if (lane == 31) wsum[wid] = x;
        __syncthreads();
        if (wid == 0) {
            int s = wsum[lane];
            #pragma unroll
            for (int o = 1; o < 32; o <<= 1) {
                int y = __shfl_up_sync(0xffffffffu, s, o);
                if (lane >= o) s += y;
            }
            wsum[lane] = s;
        }
        __syncthreads();
        int warp_off = (wid > 0) ? wsum[wid - 1] : 0;
        int excl = s_carry + warp_off + x - v;
        if (i < NN) { g_off[i] = excl; g_cur[i] = excl; }
        __syncthreads();
        if (tid == 1023) s_carry += warp_off + x;
        __syncthreads();
    }
    if (tid == 0) g_off[NN] = s_carry;
}

__global__ void scatter_kernel(const int* __restrict__ ei)
{
    int e = blockIdx.x * blockDim.x + threadIdx.x;
    if (e >= EE) return;
    int d = ei[EE + e];
    int p = atomicAdd(&g_cur[d], 1);
    g_se[p] = make_int2(ei[e], e);
}

// ---------------- aggregation: one warp per (node, head) ----------------
// lane owns 2 channels (float2) of the 64-wide head + 1 edge_attr dim.
// Per edge: one fused value y = q·k partial + av*qwe, single 5-step butterfly
// -> alpha; s=exp(alpha/8); accumulate den, s*v, s*A. Divide + We-matmul at end.
__global__ void agg_kernel(const float* __restrict__ edge_attr,
                           const float* __restrict__ We,
                           float* __restrict__ out)
{
    const int gw   = (blockIdx.x * blockDim.x + threadIdx.x) >> 5;
    const int lane = threadIdx.x & 31;
    const int w    = threadIdx.x >> 5;
    __shared__ float swa[8][32];
    if (gw >= 2 * NN) return;
    const int n = gw >> 1;
    const int h = gw & 1;

    const int beg = g_off[n];
    const int end = g_off[n + 1];
    const int cb  = h * 64 + lane * 2;

    const float2 qv = *(const float2*)&g_q[(size_t)n * HC + cb];
    const float  qw = g_qwe[n * 64 + h * 32 + lane];

    float ax = 0.f, ay = 0.f, wa = 0.f, den = 0.f;

    int2 se = (beg < end) ? g_se[beg] : make_int2(0, 0);
    for (int i = beg; i < end; i++) {
        const int2 cur = se;
        if (i + 1 < end) se = g_se[i + 1];

        const float2 kv = *(const float2*)&g_k[(size_t)cur.x * HC + cb];
        const float  av = edge_attr[(size_t)cur.y * ED + lane];

        float yv = qv.x * kv.x + qv.y * kv.y + av * qw;
        yv += __shfl_xor_sync(0xffffffffu, yv, 16);
        yv += __shfl_xor_sync(0xffffffffu, yv, 8);
        yv += __shfl_xor_sync(0xffffffffu, yv, 4);
        yv += __shfl_xor_sync(0xffffffffu, yv, 2);
        yv += __shfl_xor_sync(0xffffffffu, yv, 1);

        const float sE = __expf(yv * 0.125f);
        den += sE;
        const float2 vv = *(const float2*)&g_v[(size_t)cur.x * HC + cb];
        ax += sE * vv.x;
        ay += sE * vv.y;
        wa += sE * av;
    }

    swa[w][lane] = wa;
    __syncwarp();
    const float inv = 1.0f / (den + 1e-16f);

    float ws0 = 0.f, ws1 = 0.f;
    #pragma unroll
    for (int d = 0; d < ED; d++) {
        const float wd = swa[w][d];
        const float2 wv = *(const float2*)&We[d * HC + cb];
        ws0 += wd * wv.x;
        ws1 += wd * wv.y;
    }

    float2 o = *(float2*)&out[(size_t)n * HC + cb];
    o.x += (ax + ws0) * inv;
    o.y += (ay + ws1) * inv;
    *(float2*)&out[(size_t)n * HC + cb] = o;
}

// ---------------- launch ----------------
extern "C" void kernel_launch(void* const* d_in, const int* in_sizes, int n_in,
                              void* d_out, int out_size)
{
    const float* x     = (const float*)d_in[0];
    const int*   ei    = (const int*)  d_in[1];
    const float* ea    = (const float*)d_in[2];
    const float* Wq    = (const float*)d_in[3];
    const float* bq    = (const float*)d_in[4];
    const float* Wk    = (const float*)d_in[5];
    const float* bk    = (const float*)d_in[6];
    const float* Wv    = (const float*)d_in[7];
    const float* bv    = (const float*)d_in[8];
    const float* We    = (const float*)d_in[9];
    const float* Wskip = (const float*)d_in[10];
    const float* bskip = (const float*)d_in[11];
    float* out = (float*)d_out;

    cudaFuncSetAttribute(gemm_kernel, cudaFuncAttributeMaxDynamicSharedMemorySize, GEMM_SMEM);

    prep_x_kernel<<<(NPAD * 128 + 255) / 256, 256>>>(x);
    prep_w_kernel<<<(640 * 128 + 255) / 256, 256>>>(Wq, Wk, Wv, Wskip);
    prep_qe_kernel<<<(64 * 128 + 255) / 256, 256>>>(Wq, bq, We);

    dim3 gg(NPAD / 128, 5);
    gemm_kernel<<<gg, 256, GEMM_SMEM>>>(bq, bk, bv, bskip, out);

    zero_deg_kernel<<<(NN + 255) / 256, 256>>>();
    hist_kernel<<<(EE + 255) / 256, 256>>>(ei);
    scan_kernel<<<1, 1024>>>();
    scatter_kernel<<<(EE + 255) / 256, 256>>>(ei);

    agg_kernel<<<(2 * NN * 32 + 255) / 256, 256>>>(ea, We, out);
}

// round 16
// speedup vs baseline: 1.3667x; 1.3667x over previous
#include <cuda_runtime.h>
#include <cuda_bf16.h>
#include <cstdint>

#define NN   50000
#define NPAD 50048
#define EE   800000
#define HC   128
#define CCH  64
#define ED   32

// ---- scratch (static __device__ arrays; no allocations allowed) ----
__device__ __align__(256) __nv_bfloat16 g_xh[NPAD * 128];
__device__ __align__(256) __nv_bfloat16 g_xl[NPAD * 128];
__device__ __align__(256) __nv_bfloat16 g_Bh[640 * 128];   // [out_col][k]; rows 512-575 = Wqe, 576-639 = 0
__device__ __align__(256) __nv_bfloat16 g_Bl[640 * 128];
__device__ float g_bqe[64];
__device__ float g_q[NN * HC];
__device__ float g_k[NN * HC];
__device__ float g_v[NN * HC];
__device__ float g_qwe[NN * 64];      // [n][h*32+d]
__device__ int   g_deg[NN];
__device__ int   g_off[NN + 1];
__device__ int   g_cur[NN];
__device__ int2  g_se[EE];            // (src, eid) CSR-sorted by dst

// ================= prep: split-bf16 conversion =================
__global__ void prep_x_kernel(const float* __restrict__ x)
{
    int idx = blockIdx.x * blockDim.x + threadIdx.x;
    if (idx >= NPAD * 128) return;
    float v = (idx < NN * 128) ? x[idx] : 0.f;
    __nv_bfloat16 hi = __float2bfloat16(v);
    g_xh[idx] = hi;
    g_xl[idx] = __float2bfloat16(v - __bfloat162float(hi));
}

// rows 0-511: split transposed {Wq,Wk,Wv,Wskip}; rows 576-639: zero.
__global__ void prep_w_kernel(const float* __restrict__ Wq, const float* __restrict__ Wk,
                              const float* __restrict__ Wv, const float* __restrict__ Wskip)
{
    int idx = blockIdx.x * blockDim.x + threadIdx.x;
    if (idx >= 640 * 128) return;
    int n = idx >> 7, k = idx & 127;
    if (n >= 576) { g_Bh[idx] = __float2bfloat16(0.f); g_Bl[idx] = __float2bfloat16(0.f); return; }
    if (n >= 512) return;   // filled by prep_qe
    int m = n >> 7, col = n & 127;
    const float* W = (m == 0) ? Wq : (m == 1) ? Wk : (m == 2) ? Wv : Wskip;
    float v = W[k * 128 + col];
    __nv_bfloat16 hi = __float2bfloat16(v);
    g_Bh[idx] = hi;
    g_Bl[idx] = __float2bfloat16(v - __bfloat162float(hi));
}

// Wqe[k, h*32+d] = sum_c Wq[k, h*64+c] * We[d, h*64+c];  bqe[h*32+d] = sum_c bq[h*64+c]*We[d,h*64+c]
__global__ void prep_qe_kernel(const float* __restrict__ Wq, const float* __restrict__ bq,
                               const float* __restrict__ We)
{
    int idx = blockIdx.x * blockDim.x + threadIdx.x;
    if (idx >= 64 * 128) return;
    int j = idx >> 7, kk = idx & 127;     // j = h*32+d
    int h = j >> 5, d = j & 31;
    const float* wq = &Wq[kk * 128 + h * 64];
    const float* we = &We[d * 128 + h * 64];
    float s = 0.f;
    #pragma unroll
    for (int c = 0; c < 64; c++) s += wq[c] * we[c];
    __nv_bfloat16 hi = __float2bfloat16(s);
    g_Bh[(512 + j) * 128 + kk] = hi;
    g_Bl[(512 + j) * 128 + kk] = __float2bfloat16(s - __bfloat162float(hi));
    if (idx < 64) {
        int hh = idx >> 5, dd = idx & 31;
        float b = 0.f;
        #pragma unroll
        for (int c = 0; c < 64; c++) b += bq[hh * 64 + c] * We[dd * 128 + hh * 64 + c];
        g_bqe[idx] = b;
    }
}

// ================= fused projection GEMM via mma.sync (HMMA bf16) =================
// grid = (NPAD/128, 5); y: 0=q 1=k 2=v 3=skip 4=qwe(N=64). Split-bf16 fp32-acc.
// 512 threads, 16 warps, warp tile 32x32 -> ~90 regs/thread, 2x warp residency vs R13.
#define PA 136
#define A_TILE_B  (128 * PA * 2)
#define OFF_XH    0
#define OFF_XL    (A_TILE_B)
#define OFF_BHH   (2 * A_TILE_B)
#define OFF_BLL   (3 * A_TILE_B)
#define OFF_BIAS  (4 * A_TILE_B)
#define GEMM_SMEM (OFF_BIAS + 512)

__device__ __forceinline__ void mma16816(float* d, const uint32_t* a, const uint32_t* b)
{
    asm volatile(
        "mma.sync.aligned.m16n8k16.row.col.f32.bf16.bf16.f32 "
        "{%0,%1,%2,%3}, {%4,%5,%6,%7}, {%8,%9}, {%0,%1,%2,%3};"
        : "+f"(d[0]), "+f"(d[1]), "+f"(d[2]), "+f"(d[3])
        : "r"(a[0]), "r"(a[1]), "r"(a[2]), "r"(a[3]), "r"(b[0]), "r"(b[1]));
}

__global__ void __launch_bounds__(512, 1)
gemm_kernel(const float* __restrict__ bq, const float* __restrict__ bk,
            const float* __restrict__ bv, const float* __restrict__ bskip,
            float* __restrict__ out)
{
    extern __shared__ char sm[];
    __nv_bfloat16* Axh = (__nv_bfloat16*)(sm + OFF_XH);
    __nv_bfloat16* Axl = (__nv_bfloat16*)(sm + OFF_XL);
    __nv_bfloat16* Bsh = (__nv_bfloat16*)(sm + OFF_BHH);
    __nv_bfloat16* Bsl = (__nv_bfloat16*)(sm + OFF_BLL);
    float* biasS = (float*)(sm + OFF_BIAS);

    const int tid  = threadIdx.x;
    const int wid  = tid >> 5;
    const int lane = tid & 31;
    const int m0   = blockIdx.x * 128;
    const int y    = blockIdx.y;
    const int n0   = y * 128;

    for (int u = tid; u < 2048; u += 512) {
        int r = u >> 4, c = (u & 15) * 8;
        size_t go = (size_t)(m0 + r) * 128 + c;
        *(uint4*)&Axh[r * PA + c] = *(const uint4*)&g_xh[go];
        *(uint4*)&Axl[r * PA + c] = *(const uint4*)&g_xl[go];
    }
    for (int u = tid; u < 2048; u += 512) {
        int r = u >> 4, c = (u & 15) * 8;
        size_t go = (size_t)(n0 + r) * 128 + c;
        *(uint4*)&Bsh[r * PA + c] = *(const uint4*)&g_Bh[go];
        *(uint4*)&Bsl[r * PA + c] = *(const uint4*)&g_Bl[go];
    }
    if (tid < 128) {
        float b;
        if      (y == 0) b = bq[tid];
        else if (y == 1) b = bk[tid];
        else if (y == 2) b = bv[tid];
        else if (y == 3) b = bskip[tid];
        else             b = (tid < 64) ? g_bqe[tid] : 0.f;
        biasS[tid] = b;
    }
    __syncthreads();

    const int wm = wid & 3;      // 32-row quadrant
    const int wn = wid >> 2;     // 32-col quadrant
    const int g  = lane >> 2;
    const int t  = lane & 3;

    float acc[2][4][4];
    #pragma unroll
    for (int i = 0; i < 2; i++)
        #pragma unroll
        for (int j = 0; j < 4; j++)
            #pragma unroll
            for (int l = 0; l < 4; l++) acc[i][j][l] = 0.f;

    const __nv_bfloat16* Ap[3] = { Axh, Axl, Axh };
    const __nv_bfloat16* Bp[3] = { Bsh, Bsh, Bsl };

    #pragma unroll
    for (int p = 0; p < 3; p++) {
        const __nv_bfloat16* As = Ap[p];
        const __nv_bfloat16* Bs = Bp[p];
        #pragma unroll
        for (int ks = 0; ks < 8; ks++) {
            const int k0 = ks * 16;
            uint32_t a[2][4], b[4][2];
            #pragma unroll
            for (int mt = 0; mt < 2; mt++) {
                const int rm = wm * 32 + mt * 16 + g;
                a[mt][0] = *(const uint32_t*)&As[rm * PA + k0 + t * 2];
                a[mt][1] = *(const uint32_t*)&As[(rm + 8) * PA + k0 + t * 2];
                a[mt][2] = *(const uint32_t*)&As[rm * PA + k0 + t * 2 + 8];
                a[mt][3] = *(const uint32_t*)&As[(rm + 8) * PA + k0 + t * 2 + 8];
            }
            #pragma unroll
            for (int nt = 0; nt < 4; nt++) {
                const int cn = wn * 32 + nt * 8 + g;
                b[nt][0] = *(const uint32_t*)&Bs[cn * PA + k0 + t * 2];
                b[nt][1] = *(const uint32_t*)&Bs[cn * PA + k0 + t * 2 + 8];
            }
            #pragma unroll
            for (int mt = 0; mt < 2; mt++)
                #pragma unroll
                for (int nt = 0; nt < 4; nt++)
                    mma16816(acc[mt][nt], a[mt], b[nt]);
        }
    }

    // epilogue: direct biased float2 stores
    float* dst; int stride, ncols;
    if      (y == 0) { dst = g_q;   stride = 128; ncols = 128; }
    else if (y == 1) { dst = g_k;   stride = 128; ncols = 128; }
    else if (y == 2) { dst = g_v;   stride = 128; ncols = 128; }
    else if (y == 3) { dst = out;   stride = 128; ncols = 128; }
    else             { dst = g_qwe; stride = 64;  ncols = 64;  }

    #pragma unroll
    for (int mt = 0; mt < 2; mt++) {
        const int r0 = m0 + wm * 32 + mt * 16 + g;
        #pragma unroll
        for (int nt = 0; nt < 4; nt++) {
            const int c = wn * 32 + nt * 8 + t * 2;
            if (c >= ncols) continue;
            const float b0 = biasS[c], b1 = biasS[c + 1];
            if (r0 < NN)
                *(float2*)&dst[(size_t)r0 * stride + c] =
                    make_float2(acc[mt][nt][0] + b0, acc[mt][nt][1] + b1);
            if (r0 + 8 < NN)
                *(float2*)&dst[(size_t)(r0 + 8) * stride + c] =
                    make_float2(acc[mt][nt][2] + b0, acc[mt][nt][3] + b1);
        }
    }
}

// ---------------- CSR build ----------------
__global__ void zero_deg_kernel()
{
    int i = blockIdx.x * blockDim.x + threadIdx.x;
    if (i < NN) g_deg[i] = 0;
}

__global__ void hist_kernel(const int* __restrict__ ei)
{
    int e = blockIdx.x * blockDim.x + threadIdx.x;
    if (e < EE) atomicAdd(&g_deg[ei[EE + e]], 1);
}

__global__ void scan_kernel()
{
    const int tid  = threadIdx.x;
    const int lane = tid & 31;
    const int wid  = tid >> 5;
    __shared__ int wsum[32];
    __shared__ int s_carry;
    if (tid == 0) s_carry = 0;
    __syncthreads();

    for (int base = 0; base < NN; base += 1024) {
        int i = base + tid;
        int v = (i < NN) ? g_deg[i] : 0;

        int x = v;
        #pragma unroll
        for (int o = 1; o < 32; o <<= 1) {
            int y = __shfl_up_sync(0xffffffffu, x, o);
            if (lane >= o) x += y;
        }
        if (lane == 31) wsum[wid] = x;
        __syncthreads();
        if (wid == 0) {
            int s = wsum[lane];
            #pragma unroll
            for (int o = 1; o < 32; o <<= 1) {
                int y = __shfl_up_sync(0xffffffffu, s, o);
                if (lane >= o) s += y;
            }
            wsum[lane] = s;
        }
        __syncthreads();
        int warp_off = (wid > 0) ? wsum[wid - 1] : 0;
        int excl = s_carry + warp_off + x - v;
        if (i < NN) { g_off[i] = excl; g_cur[i] = excl; }
        __syncthreads();
        if (tid == 1023) s_carry += warp_off + x;
        __syncthreads();
    }
    if (tid == 0) g_off[NN] = s_carry;
}

__global__ void scatter_kernel(const int* __restrict__ ei)
{
    int e = blockIdx.x * blockDim.x + threadIdx.x;
    if (e >= EE) return;
    int d = ei[EE + e];
    int p = atomicAdd(&g_cur[d], 1);
    g_se[p] = make_int2(ei[e], e);
}

// ---------------- aggregation: one warp per (node, head), 2-deep pipeline ------
// lane owns 2 channels (float2) of the 64-wide head + 1 edge_attr dim.
// Loads for edge i+1 (and se for i+2) are issued BEFORE the shuffle/exp chain
// of edge i, overlapping the L2 gather latency with the reduction chain.
__global__ void agg_kernel(const float* __restrict__ edge_attr,
                           const float* __restrict__ We,
                           float* __restrict__ out)
{
    const int gw   = (blockIdx.x * blockDim.x + threadIdx.x) >> 5;
    const int lane = threadIdx.x & 31;
    const int w    = threadIdx.x >> 5;
    __shared__ float swa[8][32];
    if (gw >= 2 * NN) return;
    const int n = gw >> 1;
    const int h = gw & 1;

    const int beg = g_off[n];
    const int end = g_off[n + 1];
    const int cb  = h * 64 + lane * 2;

    const float2 qv = *(const float2*)&g_q[(size_t)n * HC + cb];
    const float  qw = g_qwe[n * 64 + h * 32 + lane];

    float ax = 0.f, ay = 0.f, wa = 0.f, den = 0.f;

    int2 seB;
    float2 kvA, vvA; float avA;
    if (beg < end) {
        int2 seA = g_se[beg];
        kvA = *(const float2*)&g_k[(size_t)seA.x * HC + cb];
        vvA = *(const float2*)&g_v[(size_t)seA.x * HC + cb];
        avA = edge_attr[(size_t)seA.y * ED + lane];
        if (beg + 1 < end) seB = g_se[beg + 1];
    }

    for (int i = beg; i < end; i++) {
        float2 kvB, vvB; float avB; int2 seC;
        const bool hasB = (i + 1 < end);
        if (hasB) {
            kvB = *(const float2*)&g_k[(size_t)seB.x * HC + cb];
            vvB = *(const float2*)&g_v[(size_t)seB.x * HC + cb];
            avB = edge_attr[(size_t)seB.y * ED + lane];
            if (i + 2 < end) seC = g_se[i + 2];
        }

        float yv = qv.x * kvA.x + qv.y * kvA.y + avA * qw;
        yv += __shfl_xor_sync(0xffffffffu, yv, 16);
        yv += __shfl_xor_sync(0xffffffffu, yv, 8);
        yv += __shfl_xor_sync(0xffffffffu, yv, 4);
        yv += __shfl_xor_sync(0xffffffffu, yv, 2);
        yv += __shfl_xor_sync(0xffffffffu, yv, 1);

        const float sE = __expf(yv * 0.125f);
        den += sE;
        ax += sE * vvA.x;
        ay += sE * vvA.y;
        wa += sE * avA;

        if (hasB) { kvA = kvB; vvA = vvB; avA = avB; seB = seC; }
    }

    swa[w][lane] = wa;
    __syncwarp();
    const float inv = 1.0f / (den + 1e-16f);

    float ws0 = 0.f, ws1 = 0.f;
    #pragma unroll
    for (int d = 0; d < ED; d++) {
        const float wd = swa[w][d];
        const float2 wv = *(const float2*)&We[d * HC + cb];
        ws0 += wd * wv.x;
        ws1 += wd * wv.y;
    }

    float2 o = *(float2*)&out[(size_t)n * HC + cb];
    o.x += (ax + ws0) * inv;
    o.y += (ay + ws1) * inv;
    *(float2*)&out[(size_t)n * HC + cb] = o;
}

// ---------------- launch ----------------
extern "C" void kernel_launch(void* const* d_in, const int* in_sizes, int n_in,
                              void* d_out, int out_size)
{
    const float* x     = (const float*)d_in[0];
    const int*   ei    = (const int*)  d_in[1];
    const float* ea    = (const float*)d_in[2];
    const float* Wq    = (const float*)d_in[3];
    const float* bq    = (const float*)d_in[4];
    const float* Wk    = (const float*)d_in[5];
    const float* bk    = (const float*)d_in[6];
    const float* Wv    = (const float*)d_in[7];
    const float* bv    = (const float*)d_in[8];
    const float* We    = (const float*)d_in[9];
    const float* Wskip = (const float*)d_in[10];
    const float* bskip = (const float*)d_in[11];
    float* out = (float*)d_out;

    cudaFuncSetAttribute(gemm_kernel, cudaFuncAttributeMaxDynamicSharedMemorySize, GEMM_SMEM);

    prep_x_kernel<<<(NPAD * 128 + 255) / 256, 256>>>(x);
    prep_w_kernel<<<(640 * 128 + 255) / 256, 256>>>(Wq, Wk, Wv, Wskip);
    prep_qe_kernel<<<(64 * 128 + 255) / 256, 256>>>(Wq, bq, We);

    dim3 gg(NPAD / 128, 5);
    gemm_kernel<<<gg, 512, GEMM_SMEM>>>(bq, bk, bv, bskip, out);

    zero_deg_kernel<<<(NN + 255) / 256, 256>>>();
    hist_kernel<<<(EE + 255) / 256, 256>>>(ei);
    scan_kernel<<<1, 1024>>>();
    scatter_kernel<<<(EE + 255) / 256, 256>>>(ei);

    agg_kernel<<<(2 * NN * 32 + 255) / 256, 256>>>(ea, We, out);
}